// round 2
// baseline (speedup 1.0000x reference)
#include <cuda_runtime.h>
#include <math.h>

#define BN   4
#define NP   4096
#define CC   128
#define KN1  16
#define KN2  8
#define TD   64
#define CIN  262
#define KZ   131          // 3 + C
#define MR   384          // 6 * 64 rows: Pq Pk Pv Sq Sk Sv

// ---------------- scratch (static device memory; no allocs) ----------------
__device__ float d_Ut[KZ * MR];               // [k][r]  k-major weight matrix
__device__ float d_Ub[MR];                    // bias per row (0 for P rows)
__device__ float d_w1t[TD * CC];              // w1 transposed [m][c]
__device__ float d_sq[BN * NP];               // per-point |xyz|^2
__device__ float d_PS[(size_t)BN * NP * MR];  // [b][n][384]
__device__ int   d_knn[BN * NP * KN1];        // 16 neighbor idx per point

// ---------------- kernel 0: prep ----------------
__global__ void prep_kernel(const float* __restrict__ xyz,
                            const float* __restrict__ wq, const float* __restrict__ bq,
                            const float* __restrict__ wk, const float* __restrict__ bk,
                            const float* __restrict__ wv, const float* __restrict__ bv,
                            const float* __restrict__ w1) {
    int stride = gridDim.x * blockDim.x;
    int tid0 = blockIdx.x * blockDim.x + threadIdx.x;

    // Ut[c][r]: decomposed weights
    for (int i = tid0; i < KZ * MR; i += stride) {
        int c = i / MR, r = i % MR;
        int g = r >> 6, o = r & 63;
        int gs = g % 3;
        const float* w = (gs == 0) ? wq : (gs == 1) ? wk : wv;
        float val;
        if (g < 3) {   // P rows: [Wa | Wc]
            val = (c < 3) ? w[o * CIN + c] : w[o * CIN + 6 + (c - 3)];
        } else {       // S rows: [Wb-Wa | Wd-Wc]
            val = (c < 3) ? (w[o * CIN + 3 + c] - w[o * CIN + c])
                          : (w[o * CIN + 134 + (c - 3)] - w[o * CIN + 6 + (c - 3)]);
        }
        d_Ut[i] = val;
    }
    // Ub
    for (int i = tid0; i < MR; i += stride) {
        int g = i >> 6, o = i & 63;
        d_Ub[i] = (g == 3) ? bq[o] : (g == 4) ? bk[o] : (g == 5) ? bv[o] : 0.0f;
    }
    // w1 transpose: w1t[m*CC + c] = w1[c*TD + m]
    for (int i = tid0; i < TD * CC; i += stride) {
        int m = i / CC, c = i % CC;
        d_w1t[i] = w1[c * TD + m];
    }
    // squared norms
    for (int i = tid0; i < BN * NP; i += stride) {
        int b = i / NP, n = i % NP;
        const float* xb = xyz + (size_t)b * 3 * NP;
        float x = xb[n], y = xb[NP + n], z = xb[2 * NP + n];
        d_sq[i] = x * x + y * y + z * z;
    }
}

// ---------------- kernel 1: PS GEMM  [384 x 131] @ [131 x 4096] per batch ----------------
#define GK 44
#define TS 68
__global__ __launch_bounds__(256) void gemm_kernel(const float* __restrict__ xyz,
                                                   const float* __restrict__ feature) {
    __shared__ float As[GK * TS];
    __shared__ float Zs[GK * TS];
    int b  = blockIdx.z;
    int mb = blockIdx.y * 64;
    int nb = blockIdx.x * 64;
    int tid = threadIdx.x;
    int tx = tid & 15, ty = tid >> 4;

    float acc[4][4] = {};
    for (int kb = 0; kb < KZ; kb += GK) {
        int kc = min(GK, KZ - kb);
        __syncthreads();
        for (int i = tid; i < kc * 64; i += 256) {
            int k = i >> 6, m = i & 63;
            As[k * TS + m] = d_Ut[(kb + k) * MR + mb + m];
            int row = kb + k;
            const float* src = (row < 3) ? (xyz + ((size_t)b * 3 + row) * NP)
                                         : (feature + ((size_t)b * CC + (row - 3)) * NP);
            Zs[k * TS + m] = src[nb + m];
        }
        __syncthreads();
        #pragma unroll 4
        for (int k = 0; k < kc; ++k) {
            float4 a4 = *(const float4*)(As + k * TS + ty * 4);
            float4 z4 = *(const float4*)(Zs + k * TS + tx * 4);
            float ar[4] = {a4.x, a4.y, a4.z, a4.w};
            float zr[4] = {z4.x, z4.y, z4.z, z4.w};
            #pragma unroll
            for (int i2 = 0; i2 < 4; i2++)
                #pragma unroll
                for (int j2 = 0; j2 < 4; j2++)
                    acc[i2][j2] = fmaf(zr[i2], ar[j2], acc[i2][j2]);
        }
    }
    float4 ub4 = *(const float4*)(d_Ub + mb + ty * 4);
    #pragma unroll
    for (int i2 = 0; i2 < 4; i2++) {
        float4 o4;
        o4.x = acc[i2][0] + ub4.x;
        o4.y = acc[i2][1] + ub4.y;
        o4.z = acc[i2][2] + ub4.z;
        o4.w = acc[i2][3] + ub4.w;
        size_t n = (size_t)b * NP + nb + tx * 4 + i2;
        *(float4*)(d_PS + n * MR + mb + ty * 4) = o4;
    }
}

// ---------------- kernel 2: KNN (top-17 incl self, drop rank 0) ----------------
__global__ __launch_bounds__(256) void knn_kernel(const float* __restrict__ xyz) {
    __shared__ float sd[8 * 17 * 32];
    __shared__ int   si[8 * 17 * 32];
    int b    = blockIdx.y;
    int warp = threadIdx.x >> 5;
    int lane = threadIdx.x & 31;
    int n    = blockIdx.x * 8 + warp;

    const float* xb  = xyz + (size_t)b * 3 * NP;
    const float* sqb = d_sq + b * NP;
    float qx = __ldg(xb + n), qy = __ldg(xb + NP + n), qz = __ldg(xb + 2 * NP + n);

    const float INFF = __int_as_float(0x7f800000);
    float dl[17]; int il[17];
    #pragma unroll
    for (int t = 0; t < 17; t++) { dl[t] = INFF; il[t] = 0x7fffffff; }

    for (int c = lane; c < NP; c += 32) {
        float t = __ldg(xb + c) * qx;
        t = fmaf(__ldg(xb + NP + c), qy, t);
        t = fmaf(__ldg(xb + 2 * NP + c), qz, t);
        float key = fmaf(-2.0f, t, __ldg(sqb + c));   // sq[m] - 2*dot (same ranking as ref)
        if (key < dl[16]) {
            dl[16] = key; il[16] = c;
            #pragma unroll
            for (int t2 = 16; t2 > 0; --t2) {
                if (dl[t2] < dl[t2 - 1]) {
                    float td = dl[t2]; dl[t2] = dl[t2 - 1]; dl[t2 - 1] = td;
                    int   ti = il[t2]; il[t2] = il[t2 - 1]; il[t2 - 1] = ti;
                }
            }
        }
    }

    int base = warp * 544 + lane * 17;
    #pragma unroll
    for (int t = 0; t < 17; t++) { sd[base + t] = dl[t]; si[base + t] = il[t]; }
    __syncwarp();

    int p = 0;
    float hk = dl[0]; int hi = il[0];
    int* outp = d_knn + ((size_t)b * NP + n) * KN1;
    for (int r = 0; r < 17; r++) {
        float wkk = hk; int wii = hi;
        #pragma unroll
        for (int off = 16; off; off >>= 1) {
            float ok = __shfl_xor_sync(0xffffffffu, wkk, off);
            int   oi = __shfl_xor_sync(0xffffffffu, wii, off);
            if (ok < wkk || (ok == wkk && oi < wii)) { wkk = ok; wii = oi; }
        }
        if (r > 0 && lane == 0) outp[r - 1] = wii;
        if (hi == wii) {
            p++;
            if (p < 17) { hk = sd[base + p]; hi = si[base + p]; }
            else        { hk = INFF; hi = 0x7fffffff; }
        }
    }
}

// ---------------- kernel 3: attention + output (1 block / point) ----------------
#define ST 65
__global__ __launch_bounds__(128) void attn_kernel(const float* __restrict__ feature,
                                                   const float* __restrict__ b1,
                                                   float* __restrict__ out) {
    __shared__ float Ssm[3][64];     // Sq_full, Sk_full, Sv_full
    __shared__ int   idxsm[16];
    __shared__ float qsm[8 * ST], ksm[16 * ST], vsm[16 * ST];
    __shared__ float psm[128], ssm[16], resm[64];

    int bf = blockIdx.x;
    int b = bf >> 12;
    int f = bf & 4095;
    int tid = threadIdx.x;

    const float* psb = d_PS + ((size_t)b * NP + f) * MR;
    if (tid < 64) {
        Ssm[0][tid] = psb[192 + tid];
        Ssm[1][tid] = psb[256 + tid];
        Ssm[2][tid] = psb[320 + tid];
    }
    if (tid < 16) idxsm[tid] = d_knn[((size_t)b * NP + f) * KN1 + tid];
    __syncthreads();

    // gather: k = Pk[idx]+Sk, v = Pv[idx] (raw), q = Pq[idx1]+Sq
    for (int i = tid; i < 40 * 64; i += 128) {
        int row = i >> 6, c = i & 63;
        if (row < 16) {
            const float* p = d_PS + ((size_t)b * NP + idxsm[row]) * MR;
            ksm[row * ST + c] = p[64 + c] + Ssm[1][c];
        } else if (row < 32) {
            int j = row - 16;
            const float* p = d_PS + ((size_t)b * NP + idxsm[j]) * MR;
            vsm[j * ST + c] = p[128 + c];
        } else {
            int nn = row - 32;
            const float* p = d_PS + ((size_t)b * NP + idxsm[nn]) * MR;
            qsm[nn * ST + c] = p[c] + Ssm[0][c];
        }
    }
    __syncthreads();

    // attn[n][j] = q_n . k_j   (n = tid>>4 in [0,8), j = tid&15)
    int nq = tid >> 4, j = tid & 15;
    float a = 0.0f;
    #pragma unroll
    for (int c = 0; c < 64; c++) a = fmaf(qsm[nq * ST + c], ksm[j * ST + c], a);

    // softmax over j within 16-lane groups
    float mx = a;
    #pragma unroll
    for (int off = 8; off; off >>= 1) mx = fmaxf(mx, __shfl_xor_sync(0xffffffffu, mx, off));
    float e = expf(a - mx);
    float sum = e;
    #pragma unroll
    for (int off = 8; off; off >>= 1) sum += __shfl_xor_sync(0xffffffffu, sum, off);
    psm[nq * 16 + j] = e / sum;
    __syncthreads();

    if (tid < 16) {
        float s = 0.0f;
        #pragma unroll
        for (int nn = 0; nn < 8; nn++) s += psm[nn * 16 + tid];
        ssm[tid] = s;
    }
    __syncthreads();

    // res[m] = sum_j s_j * Pv[m, i_j] + 8 * Sv_full[m]   (sum_j s_j == 8)
    if (tid < 64) {
        float r_ = 8.0f * Ssm[2][tid];
        #pragma unroll
        for (int jj = 0; jj < 16; jj++) r_ = fmaf(ssm[jj], vsm[jj * ST + tid], r_);
        resm[tid] = r_;
    }
    __syncthreads();

    // out[c] = w1[c,:] . res + b1[c] + feature[c]
    float acc = __ldg(b1 + tid);
    #pragma unroll
    for (int m = 0; m < 64; m++) acc = fmaf(d_w1t[m * CC + tid], resm[m], acc);
    size_t oi = ((size_t)b * CC + tid) * NP + f;
    out[oi] = acc + __ldg(feature + oi);
}

// ---------------- launch ----------------
extern "C" void kernel_launch(void* const* d_in, const int* in_sizes, int n_in,
                              void* d_out, int out_size) {
    const float* feature = (const float*)d_in[0];
    const float* xyz     = (const float*)d_in[1];
    const float* wq      = (const float*)d_in[2];
    const float* bq      = (const float*)d_in[3];
    const float* wk      = (const float*)d_in[4];
    const float* bk      = (const float*)d_in[5];
    const float* wv      = (const float*)d_in[6];
    const float* bv      = (const float*)d_in[7];
    const float* w1      = (const float*)d_in[8];
    const float* b1      = (const float*)d_in[9];
    float* out = (float*)d_out;

    prep_kernel<<<96, 256>>>(xyz, wq, bq, wk, bk, wv, bv, w1);
    gemm_kernel<<<dim3(64, 6, 4), 256>>>(xyz, feature);
    knn_kernel<<<dim3(512, 4), 256>>>(xyz);
    attn_kernel<<<BN * NP, 128>>>(feature, b1, out);
}

// round 5
// speedup vs baseline: 1.1552x; 1.1552x over previous
#include <cuda_runtime.h>
#include <math.h>

#define BN   4
#define NP   4096
#define CC   128
#define KN1  16
#define TD   64
#define CIN  262
#define KZ   131          // 3 + C
#define MR   384          // 6 * 64 rows: Pq Pk Pv Sq Sk Sv
#define FULLM 0xffffffffu

// ---------------- scratch (static device memory; no allocs) ----------------
__device__ float d_Ut[KZ * MR];               // [k][r]
__device__ float d_Ub[MR];
__device__ float d_sq[BN * NP];               // per-point |xyz|^2
__device__ float d_PS[(size_t)BN * NP * MR];  // [b][n][384] point-major
__device__ int   d_knn[BN * NP * KN1];
__device__ float d_res[(size_t)BN * NP * TD]; // [p][64]

// ---------------- kernel 0: prep (same as R1, minus w1t) ----------------
__global__ void prep_kernel(const float* __restrict__ xyz,
                            const float* __restrict__ wq, const float* __restrict__ bq,
                            const float* __restrict__ wk, const float* __restrict__ bk,
                            const float* __restrict__ wv, const float* __restrict__ bv) {
    int stride = gridDim.x * blockDim.x;
    int tid0 = blockIdx.x * blockDim.x + threadIdx.x;
    for (int i = tid0; i < KZ * MR; i += stride) {
        int c = i / MR, r = i % MR;
        int g = r >> 6, o = r & 63;
        int gs = g % 3;
        const float* w = (gs == 0) ? wq : (gs == 1) ? wk : wv;
        float val;
        if (g < 3) {
            val = (c < 3) ? w[o * CIN + c] : w[o * CIN + 6 + (c - 3)];
        } else {
            val = (c < 3) ? (w[o * CIN + 3 + c] - w[o * CIN + c])
                          : (w[o * CIN + 134 + (c - 3)] - w[o * CIN + 6 + (c - 3)]);
        }
        d_Ut[i] = val;
    }
    for (int i = tid0; i < MR; i += stride) {
        int g = i >> 6, o = i & 63;
        d_Ub[i] = (g == 3) ? bq[o] : (g == 4) ? bk[o] : (g == 5) ? bv[o] : 0.0f;
    }
    for (int i = tid0; i < BN * NP; i += stride) {
        int b = i / NP, n = i % NP;
        const float* xb = xyz + (size_t)b * 3 * NP;
        float x = xb[n], y = xb[NP + n], z = xb[2 * NP + n];
        d_sq[i] = x * x + y * y + z * z;
    }
}

// ---------------- kernel 1: PS GEMM (unchanged from R1) ----------------
#define GK 44
#define TS 68
__global__ __launch_bounds__(256) void gemm_kernel(const float* __restrict__ xyz,
                                                   const float* __restrict__ feature) {
    __shared__ float As[GK * TS];
    __shared__ float Zs[GK * TS];
    int b  = blockIdx.z;
    int mb = blockIdx.y * 64;
    int nb = blockIdx.x * 64;
    int tid = threadIdx.x;
    int tx = tid & 15, ty = tid >> 4;

    float acc[4][4] = {};
    for (int kb = 0; kb < KZ; kb += GK) {
        int kc = min(GK, KZ - kb);
        __syncthreads();
        for (int i = tid; i < kc * 64; i += 256) {
            int k = i >> 6, m = i & 63;
            As[k * TS + m] = d_Ut[(kb + k) * MR + mb + m];
            int row = kb + k;
            const float* src = (row < 3) ? (xyz + ((size_t)b * 3 + row) * NP)
                                         : (feature + ((size_t)b * CC + (row - 3)) * NP);
            Zs[k * TS + m] = src[nb + m];
        }
        __syncthreads();
        #pragma unroll 4
        for (int k = 0; k < kc; ++k) {
            float4 a4 = *(const float4*)(As + k * TS + ty * 4);
            float4 z4 = *(const float4*)(Zs + k * TS + tx * 4);
            float ar[4] = {a4.x, a4.y, a4.z, a4.w};
            float zr[4] = {z4.x, z4.y, z4.z, z4.w};
            #pragma unroll
            for (int i2 = 0; i2 < 4; i2++)
                #pragma unroll
                for (int j2 = 0; j2 < 4; j2++)
                    acc[i2][j2] = fmaf(zr[i2], ar[j2], acc[i2][j2]);
        }
    }
    float4 ub4 = *(const float4*)(d_Ub + mb + ty * 4);
    #pragma unroll
    for (int i2 = 0; i2 < 4; i2++) {
        float4 o4;
        o4.x = acc[i2][0] + ub4.x;
        o4.y = acc[i2][1] + ub4.y;
        o4.z = acc[i2][2] + ub4.z;
        o4.w = acc[i2][3] + ub4.w;
        size_t n = (size_t)b * NP + nb + tx * 4 + i2;
        *(float4*)(d_PS + n * MR + mb + ty * 4) = o4;
    }
}

// ---------------- kernel 2: KNN (verbatim from R1 — proven on container) ----------------
__global__ __launch_bounds__(256) void knn_kernel(const float* __restrict__ xyz) {
    __shared__ float sd[8 * 17 * 32];
    __shared__ int   si[8 * 17 * 32];
    int b    = blockIdx.y;
    int warp = threadIdx.x >> 5;
    int lane = threadIdx.x & 31;
    int n    = blockIdx.x * 8 + warp;

    const float* xb  = xyz + (size_t)b * 3 * NP;
    const float* sqb = d_sq + b * NP;
    float qx = __ldg(xb + n), qy = __ldg(xb + NP + n), qz = __ldg(xb + 2 * NP + n);

    const float INFF = __int_as_float(0x7f800000);
    float dl[17]; int il[17];
    #pragma unroll
    for (int t = 0; t < 17; t++) { dl[t] = INFF; il[t] = 0x7fffffff; }

    for (int c = lane; c < NP; c += 32) {
        float t = __ldg(xb + c) * qx;
        t = fmaf(__ldg(xb + NP + c), qy, t);
        t = fmaf(__ldg(xb + 2 * NP + c), qz, t);
        float key = fmaf(-2.0f, t, __ldg(sqb + c));   // sq[m] - 2*dot (same ranking as ref)
        if (key < dl[16]) {
            dl[16] = key; il[16] = c;
            #pragma unroll
            for (int t2 = 16; t2 > 0; --t2) {
                if (dl[t2] < dl[t2 - 1]) {
                    float td = dl[t2]; dl[t2] = dl[t2 - 1]; dl[t2 - 1] = td;
                    int   ti = il[t2]; il[t2] = il[t2 - 1]; il[t2 - 1] = ti;
                }
            }
        }
    }

    int base = warp * 544 + lane * 17;
    #pragma unroll
    for (int t = 0; t < 17; t++) { sd[base + t] = dl[t]; si[base + t] = il[t]; }
    __syncwarp();

    int p = 0;
    float hk = dl[0]; int hi = il[0];
    int* outp = d_knn + ((size_t)b * NP + n) * KN1;
    for (int r = 0; r < 17; r++) {
        float wkk = hk; int wii = hi;
        #pragma unroll
        for (int off = 16; off; off >>= 1) {
            float ok = __shfl_xor_sync(FULLM, wkk, off);
            int   oi = __shfl_xor_sync(FULLM, wii, off);
            if (ok < wkk || (ok == wkk && oi < wii)) { wkk = ok; wii = oi; }
        }
        if (r > 0 && lane == 0) outp[r - 1] = wii;
        if (hi == wii) {
            p++;
            if (p < 17) { hk = sd[base + p]; hi = si[base + p]; }
            else        { hk = INFF; hi = 0x7fffffff; }
        }
    }
}

// ---------------- kernel 3: attention -> res (1 block / point, float4) ----------------
__global__ __launch_bounds__(128) void attn_kernel(float* __restrict__ resout) {
    __shared__ float4 qsm[8][17], ksm[16][17], vsm[16][17];
    __shared__ float  S_[192];       // Sq, Sk, Sv
    __shared__ int    idxsm[16];
    __shared__ float  psm[128], ssm[16];

    int p   = blockIdx.x;           // p = b*NP + f
    int tid = threadIdx.x;
    const float* psb = d_PS + (size_t)p * MR;

    if (tid < 48) ((float4*)S_)[tid] = ((const float4*)(psb + 192))[tid];
    if (tid < 16) idxsm[tid] = d_knn[(size_t)p * KN1 + tid];
    __syncthreads();

    int bbase = (p >> 12) * NP;
    for (int i = tid; i < 640; i += 128) {
        int row = i >> 4, c4 = i & 15;
        if (row < 16) {
            const float4* src = (const float4*)(d_PS + ((size_t)(bbase + idxsm[row])) * MR + 64);
            float4 a = src[c4], s = ((const float4*)(S_ + 64))[c4];
            ksm[row][c4] = make_float4(a.x + s.x, a.y + s.y, a.z + s.z, a.w + s.w);
        } else if (row < 32) {
            int j = row - 16;
            const float4* src = (const float4*)(d_PS + ((size_t)(bbase + idxsm[j])) * MR + 128);
            vsm[j][c4] = src[c4];
        } else {
            int nn = row - 32;
            const float4* src = (const float4*)(d_PS + ((size_t)(bbase + idxsm[nn])) * MR);
            float4 a = src[c4], s = ((const float4*)S_)[c4];
            qsm[nn][c4] = make_float4(a.x + s.x, a.y + s.y, a.z + s.z, a.w + s.w);
        }
    }
    __syncthreads();

    int nq = tid >> 4, j = tid & 15;
    float a = 0.0f;
    #pragma unroll
    for (int c4 = 0; c4 < 16; c4++) {
        float4 q4 = qsm[nq][c4], k4 = ksm[j][c4];
        a = fmaf(q4.x, k4.x, a); a = fmaf(q4.y, k4.y, a);
        a = fmaf(q4.z, k4.z, a); a = fmaf(q4.w, k4.w, a);
    }
    float mx = a;
    #pragma unroll
    for (int off = 8; off; off >>= 1) mx = fmaxf(mx, __shfl_xor_sync(FULLM, mx, off));
    float e = expf(a - mx);
    float sum = e;
    #pragma unroll
    for (int off = 8; off; off >>= 1) sum += __shfl_xor_sync(FULLM, sum, off);
    psm[nq * 16 + j] = e / sum;
    __syncthreads();

    if (tid < 16) {
        float s = 0.0f;
        #pragma unroll
        for (int nn = 0; nn < 8; nn++) s += psm[nn * 16 + tid];
        ssm[tid] = s;
    }
    __syncthreads();

    if (tid < 64) {
        const float* vf = (const float*)vsm;
        float r_ = 8.0f * S_[128 + tid];           // sum_j s_j == 8
        #pragma unroll
        for (int jj = 0; jj < 16; jj++) r_ = fmaf(ssm[jj], vf[jj * 68 + tid], r_);
        resout[(size_t)p * TD + tid] = r_;
    }
}

// ---------------- kernel 4: out = w1 @ res^T + b1 + feature ----------------
#define G2S 68
__global__ __launch_bounds__(256) void gemm2_kernel(const float* __restrict__ w1,
                                                    const float* __restrict__ b1,
                                                    const float* __restrict__ feature,
                                                    float* __restrict__ out) {
    __shared__ float As[TD * G2S];   // [k][c]
    __shared__ float Bs[TD * G2S];   // [k][n]
    int tid = threadIdx.x;
    int cb  = blockIdx.y * 64;
    int gp  = blockIdx.x * 64;       // global point base (64 | 4096 -> single batch)
    int tx = tid & 15, ty = tid >> 4;

    for (int i = tid; i < 64 * 64; i += 256) {
        int c = i & 63, k = i >> 6;
        As[k * G2S + c] = w1[(cb + c) * TD + k];
    }
    for (int i = tid; i < 64 * 16; i += 256) {
        int n = i >> 4, m4 = i & 15;
        float4 r4 = *(const float4*)(d_res + ((size_t)(gp + n)) * TD + m4 * 4);
        Bs[(m4 * 4 + 0) * G2S + n] = r4.x;
        Bs[(m4 * 4 + 1) * G2S + n] = r4.y;
        Bs[(m4 * 4 + 2) * G2S + n] = r4.z;
        Bs[(m4 * 4 + 3) * G2S + n] = r4.w;
    }
    __syncthreads();

    float acc[4][4] = {};  // [c][n]
    #pragma unroll 8
    for (int k = 0; k < TD; k++) {
        float4 a4 = *(const float4*)(As + k * G2S + ty * 4);
        float4 b4 = *(const float4*)(Bs + k * G2S + tx * 4);
        float ar[4] = {a4.x, a4.y, a4.z, a4.w};
        float br[4] = {b4.x, b4.y, b4.z, b4.w};
        #pragma unroll
        for (int i2 = 0; i2 < 4; i2++)
            #pragma unroll
            for (int j2 = 0; j2 < 4; j2++)
                acc[i2][j2] = fmaf(ar[i2], br[j2], acc[i2][j2]);
    }

    int b = gp >> 12;
    int f0 = (gp & 4095) + tx * 4;
    #pragma unroll
    for (int i2 = 0; i2 < 4; i2++) {
        int c = cb + ty * 4 + i2;
        float bias = __ldg(b1 + c);
        size_t addr = ((size_t)(b * CC + c)) * NP + f0;
        float4 fea = *(const float4*)(feature + addr);
        float4 o4;
        o4.x = acc[i2][0] + bias + fea.x;
        o4.y = acc[i2][1] + bias + fea.y;
        o4.z = acc[i2][2] + bias + fea.z;
        o4.w = acc[i2][3] + bias + fea.w;
        *(float4*)(out + addr) = o4;
    }
}

// ---------------- launch ----------------
extern "C" void kernel_launch(void* const* d_in, const int* in_sizes, int n_in,
                              void* d_out, int out_size) {
    const float* feature = (const float*)d_in[0];
    const float* xyz     = (const float*)d_in[1];
    const float* wq      = (const float*)d_in[2];
    const float* bq      = (const float*)d_in[3];
    const float* wk      = (const float*)d_in[4];
    const float* bk      = (const float*)d_in[5];
    const float* wv      = (const float*)d_in[6];
    const float* bv      = (const float*)d_in[7];
    const float* w1      = (const float*)d_in[8];
    const float* b1      = (const float*)d_in[9];
    float* out = (float*)d_out;

    prep_kernel<<<96, 256>>>(xyz, wq, bq, wk, bk, wv, bv);
    gemm_kernel<<<dim3(64, 6, 4), 256>>>(xyz, feature);
    knn_kernel<<<dim3(512, 4), 256>>>(xyz);

    float* resbuf;
    cudaGetSymbolAddress((void**)&resbuf, d_res);
    attn_kernel<<<BN * NP, 128>>>(resbuf);
    gemm2_kernel<<<dim3(256, 2), 256>>>(w1, b1, feature, out);
}

// round 6
// speedup vs baseline: 2.4735x; 2.1411x over previous
#include <cuda_runtime.h>
#include <math.h>

#define BN   4
#define NP   4096
#define CC   128
#define KN1  16
#define TD   64
#define CIN  262
#define KZ   131          // 3 + C
#define MR   384          // 6 * 64 rows: Pq Pk Pv Sq Sk Sv
#define FULLM 0xffffffffu

// ---------------- scratch (static device memory; no allocs) ----------------
__device__ float d_Ut[KZ * MR];               // [k][r]
__device__ float d_Ub[MR];
__device__ float d_PS[(size_t)BN * NP * MR];  // [b][n][384] point-major
__device__ int   d_knn[BN * NP * KN1];
__device__ float d_res[(size_t)BN * NP * TD]; // [p][64]

// ---------------- kernel 0: prep ----------------
__global__ void prep_kernel(const float* __restrict__ wq, const float* __restrict__ bq,
                            const float* __restrict__ wk, const float* __restrict__ bk,
                            const float* __restrict__ wv, const float* __restrict__ bv) {
    int stride = gridDim.x * blockDim.x;
    int tid0 = blockIdx.x * blockDim.x + threadIdx.x;
    for (int i = tid0; i < KZ * MR; i += stride) {
        int c = i / MR, r = i % MR;
        int g = r >> 6, o = r & 63;
        int gs = g % 3;
        const float* w = (gs == 0) ? wq : (gs == 1) ? wk : wv;
        float val;
        if (g < 3) {
            val = (c < 3) ? w[o * CIN + c] : w[o * CIN + 6 + (c - 3)];
        } else {
            val = (c < 3) ? (w[o * CIN + 3 + c] - w[o * CIN + c])
                          : (w[o * CIN + 134 + (c - 3)] - w[o * CIN + 6 + (c - 3)]);
        }
        d_Ut[i] = val;
    }
    for (int i = tid0; i < MR; i += stride) {
        int g = i >> 6, o = i & 63;
        d_Ub[i] = (g == 3) ? bq[o] : (g == 4) ? bk[o] : (g == 5) ? bv[o] : 0.0f;
    }
}

// ---------------- kernel 1: PS GEMM  [384 x 131] @ [131 x 4096] per batch ----------------
#define GK 44
#define TS 68
__global__ __launch_bounds__(256) void gemm_kernel(const float* __restrict__ xyz,
                                                   const float* __restrict__ feature) {
    __shared__ float As[GK * TS];
    __shared__ float Zs[GK * TS];
    int b  = blockIdx.z;
    int mb = blockIdx.y * 64;
    int nb = blockIdx.x * 64;
    int tid = threadIdx.x;
    int tx = tid & 15, ty = tid >> 4;

    float acc[4][4] = {};
    for (int kb = 0; kb < KZ; kb += GK) {
        int kc = min(GK, KZ - kb);
        __syncthreads();
        for (int i = tid; i < kc * 64; i += 256) {
            int k = i >> 6, m = i & 63;
            As[k * TS + m] = d_Ut[(kb + k) * MR + mb + m];
            int row = kb + k;
            const float* src = (row < 3) ? (xyz + ((size_t)b * 3 + row) * NP)
                                         : (feature + ((size_t)b * CC + (row - 3)) * NP);
            Zs[k * TS + m] = src[nb + m];
        }
        __syncthreads();
        #pragma unroll 4
        for (int k = 0; k < kc; ++k) {
            float4 a4 = *(const float4*)(As + k * TS + ty * 4);
            float4 z4 = *(const float4*)(Zs + k * TS + tx * 4);
            float ar[4] = {a4.x, a4.y, a4.z, a4.w};
            float zr[4] = {z4.x, z4.y, z4.z, z4.w};
            #pragma unroll
            for (int i2 = 0; i2 < 4; i2++)
                #pragma unroll
                for (int j2 = 0; j2 < 4; j2++)
                    acc[i2][j2] = fmaf(zr[i2], ar[j2], acc[i2][j2]);
        }
    }
    float4 ub4 = *(const float4*)(d_Ub + mb + ty * 4);
    #pragma unroll
    for (int i2 = 0; i2 < 4; i2++) {
        float4 o4;
        o4.x = acc[i2][0] + ub4.x;
        o4.y = acc[i2][1] + ub4.y;
        o4.z = acc[i2][2] + ub4.z;
        o4.w = acc[i2][3] + ub4.w;
        size_t n = (size_t)b * NP + nb + tx * 4 + i2;
        *(float4*)(d_PS + n * MR + mb + ty * 4) = o4;
    }
}

// ---------------- kernel 2: KNN — warp-distributed sorted top-17, ballot-gated ----------------
#define KTC 1024
__global__ __launch_bounds__(256) void knn_kernel(const float* __restrict__ xyz) {
    __shared__ float4 cand[KTC];
    int b    = blockIdx.y;
    int tid  = threadIdx.x;
    int warp = tid >> 5;
    int lane = tid & 31;
    int n    = blockIdx.x * 8 + warp;

    const float* xb = xyz + (size_t)b * 3 * NP;
    float qx = __ldg(xb + n), qy = __ldg(xb + NP + n), qz = __ldg(xb + 2 * NP + n);

    const float INFF = __int_as_float(0x7f800000);
    float v = INFF;        // lane l (l<17) holds rank-l key (ascending)
    int   vi = 0x7fffffff;
    float tau = INFF;      // rank-16 key, warp-uniform

    for (int t = 0; t < NP / KTC; t++) {
        int base = t * KTC;
        for (int i = tid; i < KTC; i += 256) {
            int c = base + i;
            float x = __ldg(xb + c), y = __ldg(xb + NP + c), z = __ldg(xb + 2 * NP + c);
            float sq = fmaf(x, x, fmaf(y, y, z * z));
            cand[i] = make_float4(x, y, z, sq);
        }
        __syncthreads();
        for (int s = 0; s < KTC / 32; s++) {
            int ci = base + s * 32 + lane;
            float4 cd = cand[s * 32 + lane];
            float dot = fmaf(cd.x, qx, fmaf(cd.y, qy, cd.z * qz));
            float key = fmaf(-2.0f, dot, cd.w);     // sq[m] - 2*dot (same ranking as ref)
            unsigned mask = __ballot_sync(FULLM, key < tau);
            while (mask) {                           // bounded: popcount(mask) iters max
                int src = __ffs(mask) - 1;
                mask &= mask - 1;
                float kk = __shfl_sync(FULLM, key, src);
                int   kc = __shfl_sync(FULLM, ci, src);
                if (kk < tau) {                      // recheck: tau tightened by prior inserts
                    unsigned pm = __ballot_sync(FULLM, (lane < 17) && (kk < v));
                    int pos = __ffs(pm) - 1;         // first rank whose key > kk
                    float vp = __shfl_up_sync(FULLM, v, 1);
                    int   ip = __shfl_up_sync(FULLM, vi, 1);
                    if (lane < 17 && lane >= pos) {
                        if (lane == pos) { v = kk; vi = kc; }
                        else             { v = vp; vi = ip; }
                    }
                    tau = __shfl_sync(FULLM, v, 16);
                }
            }
        }
        __syncthreads();
    }
    if (lane >= 1 && lane < 17)                      // rank 0 == self, dropped
        d_knn[((size_t)b * NP + n) * KN1 + (lane - 1)] = vi;
}

// ---------------- kernel 3: attention -> res (1 block / point, float4) ----------------
__global__ __launch_bounds__(128) void attn_kernel(float* __restrict__ resout) {
    __shared__ float4 qsm[8][17], ksm[16][17], vsm[16][17];
    __shared__ float  S_[192];       // Sq, Sk, Sv
    __shared__ int    idxsm[16];
    __shared__ float  psm[128], ssm[16];

    int p   = blockIdx.x;           // p = b*NP + f
    int tid = threadIdx.x;
    const float* psb = d_PS + (size_t)p * MR;

    if (tid < 48) ((float4*)S_)[tid] = ((const float4*)(psb + 192))[tid];
    if (tid < 16) idxsm[tid] = d_knn[(size_t)p * KN1 + tid];
    __syncthreads();

    int bbase = (p >> 12) * NP;
    for (int i = tid; i < 640; i += 128) {
        int row = i >> 4, c4 = i & 15;
        if (row < 16) {
            const float4* src = (const float4*)(d_PS + ((size_t)(bbase + idxsm[row])) * MR + 64);
            float4 a = src[c4], s = ((const float4*)(S_ + 64))[c4];
            ksm[row][c4] = make_float4(a.x + s.x, a.y + s.y, a.z + s.z, a.w + s.w);
        } else if (row < 32) {
            int j = row - 16;
            const float4* src = (const float4*)(d_PS + ((size_t)(bbase + idxsm[j])) * MR + 128);
            vsm[j][c4] = src[c4];
        } else {
            int nn = row - 32;
            const float4* src = (const float4*)(d_PS + ((size_t)(bbase + idxsm[nn])) * MR);
            float4 a = src[c4], s = ((const float4*)S_)[c4];
            qsm[nn][c4] = make_float4(a.x + s.x, a.y + s.y, a.z + s.z, a.w + s.w);
        }
    }
    __syncthreads();

    int nq = tid >> 4, j = tid & 15;
    float a = 0.0f;
    #pragma unroll
    for (int c4 = 0; c4 < 16; c4++) {
        float4 q4 = qsm[nq][c4], k4 = ksm[j][c4];
        a = fmaf(q4.x, k4.x, a); a = fmaf(q4.y, k4.y, a);
        a = fmaf(q4.z, k4.z, a); a = fmaf(q4.w, k4.w, a);
    }
    float mx = a;
    #pragma unroll
    for (int off = 8; off; off >>= 1) mx = fmaxf(mx, __shfl_xor_sync(FULLM, mx, off));
    float e = expf(a - mx);
    float sum = e;
    #pragma unroll
    for (int off = 8; off; off >>= 1) sum += __shfl_xor_sync(FULLM, sum, off);
    psm[nq * 16 + j] = e / sum;
    __syncthreads();

    if (tid < 16) {
        float s = 0.0f;
        #pragma unroll
        for (int nn = 0; nn < 8; nn++) s += psm[nn * 16 + tid];
        ssm[tid] = s;
    }
    __syncthreads();

    if (tid < 64) {
        const float* vf = (const float*)vsm;
        float r_ = 8.0f * S_[128 + tid];           // sum_j s_j == 8
        #pragma unroll
        for (int jj = 0; jj < 16; jj++) r_ = fmaf(ssm[jj], vf[jj * 68 + tid], r_);
        resout[(size_t)p * TD + tid] = r_;
    }
}

// ---------------- kernel 4: out = w1 @ res^T + b1 + feature ----------------
#define G2S 68
__global__ __launch_bounds__(256) void gemm2_kernel(const float* __restrict__ w1,
                                                    const float* __restrict__ b1,
                                                    const float* __restrict__ feature,
                                                    float* __restrict__ out) {
    __shared__ float As[TD * G2S];   // [k][c]
    __shared__ float Bs[TD * G2S];   // [k][n]
    int tid = threadIdx.x;
    int cb  = blockIdx.y * 64;
    int gp  = blockIdx.x * 64;       // global point base (64 | 4096 -> single batch)
    int tx = tid & 15, ty = tid >> 4;

    for (int i = tid; i < 64 * 64; i += 256) {
        int c = i & 63, k = i >> 6;
        As[k * G2S + c] = w1[(cb + c) * TD + k];
    }
    for (int i = tid; i < 64 * 16; i += 256) {
        int n = i >> 4, m4 = i & 15;
        float4 r4 = *(const float4*)(d_res + ((size_t)(gp + n)) * TD + m4 * 4);
        Bs[(m4 * 4 + 0) * G2S + n] = r4.x;
        Bs[(m4 * 4 + 1) * G2S + n] = r4.y;
        Bs[(m4 * 4 + 2) * G2S + n] = r4.z;
        Bs[(m4 * 4 + 3) * G2S + n] = r4.w;
    }
    __syncthreads();

    float acc[4][4] = {};  // [c][n]
    #pragma unroll 8
    for (int k = 0; k < TD; k++) {
        float4 a4 = *(const float4*)(As + k * G2S + ty * 4);
        float4 b4 = *(const float4*)(Bs + k * G2S + tx * 4);
        float ar[4] = {a4.x, a4.y, a4.z, a4.w};
        float br[4] = {b4.x, b4.y, b4.z, b4.w};
        #pragma unroll
        for (int i2 = 0; i2 < 4; i2++)
            #pragma unroll
            for (int j2 = 0; j2 < 4; j2++)
                acc[i2][j2] = fmaf(ar[i2], br[j2], acc[i2][j2]);
    }

    int b = gp >> 12;
    int f0 = (gp & 4095) + tx * 4;
    #pragma unroll
    for (int i2 = 0; i2 < 4; i2++) {
        int c = cb + ty * 4 + i2;
        float bias = __ldg(b1 + c);
        size_t addr = ((size_t)(b * CC + c)) * NP + f0;
        float4 fea = *(const float4*)(feature + addr);
        float4 o4;
        o4.x = acc[i2][0] + bias + fea.x;
        o4.y = acc[i2][1] + bias + fea.y;
        o4.z = acc[i2][2] + bias + fea.z;
        o4.w = acc[i2][3] + bias + fea.w;
        *(float4*)(out + addr) = o4;
    }
}

// ---------------- launch ----------------
extern "C" void kernel_launch(void* const* d_in, const int* in_sizes, int n_in,
                              void* d_out, int out_size) {
    const float* feature = (const float*)d_in[0];
    const float* xyz     = (const float*)d_in[1];
    const float* wq      = (const float*)d_in[2];
    const float* bq      = (const float*)d_in[3];
    const float* wk      = (const float*)d_in[4];
    const float* bk      = (const float*)d_in[5];
    const float* wv      = (const float*)d_in[6];
    const float* bv      = (const float*)d_in[7];
    const float* w1      = (const float*)d_in[8];
    const float* b1      = (const float*)d_in[9];
    float* out = (float*)d_out;

    prep_kernel<<<96, 256>>>(wq, bq, wk, bk, wv, bv);
    gemm_kernel<<<dim3(64, 6, 4), 256>>>(xyz, feature);
    knn_kernel<<<dim3(512, 4), 256>>>(xyz);

    float* resbuf;
    cudaGetSymbolAddress((void**)&resbuf, d_res);
    attn_kernel<<<BN * NP, 128>>>(resbuf);
    gemm2_kernel<<<dim3(256, 2), 256>>>(w1, b1, feature, out);
}

// round 7
// speedup vs baseline: 2.5869x; 1.0458x over previous
#include <cuda_runtime.h>
#include <math.h>

#define BN   4
#define NP   4096
#define CC   128
#define KN1  16
#define TD   64
#define CIN  262
#define KZ   131          // 3 + C
#define MR   384          // 6 * 64 rows: Pq Pk Pv Sq Sk Sv
#define FULLM 0xffffffffu

// ---------------- scratch (static device memory; no allocs) ----------------
__device__ float d_Ut[KZ * MR];               // [k][r]
__device__ float d_Ub[MR];
__device__ float d_PS[(size_t)BN * NP * MR];  // [b][n][384] point-major
__device__ int   d_knn[BN * NP * KN1];
__device__ float d_res[(size_t)BN * NP * TD]; // [p][64]

// ---------------- kernel 0: prep ----------------
__global__ void prep_kernel(const float* __restrict__ wq, const float* __restrict__ bq,
                            const float* __restrict__ wk, const float* __restrict__ bk,
                            const float* __restrict__ wv, const float* __restrict__ bv) {
    int stride = gridDim.x * blockDim.x;
    int tid0 = blockIdx.x * blockDim.x + threadIdx.x;
    for (int i = tid0; i < KZ * MR; i += stride) {
        int c = i / MR, r = i % MR;
        int g = r >> 6, o = r & 63;
        int gs = g % 3;
        const float* w = (gs == 0) ? wq : (gs == 1) ? wk : wv;
        float val;
        if (g < 3) {
            val = (c < 3) ? w[o * CIN + c] : w[o * CIN + 6 + (c - 3)];
        } else {
            val = (c < 3) ? (w[o * CIN + 3 + c] - w[o * CIN + c])
                          : (w[o * CIN + 134 + (c - 3)] - w[o * CIN + 6 + (c - 3)]);
        }
        d_Ut[i] = val;
    }
    for (int i = tid0; i < MR; i += stride) {
        int g = i >> 6, o = i & 63;
        d_Ub[i] = (g == 3) ? bq[o] : (g == 4) ? bk[o] : (g == 5) ? bv[o] : 0.0f;
    }
}

// ---------------- kernel 1: PS GEMM  [384 x 131] @ [131 x 4096] per batch ----------------
#define GK 66
#define TS 68
__global__ __launch_bounds__(256) void gemm_kernel(const float* __restrict__ xyz,
                                                   const float* __restrict__ feature) {
    __shared__ float As[GK * TS];
    __shared__ float Zs[GK * TS];
    int b  = blockIdx.z;
    int mb = blockIdx.y * 64;
    int nb = blockIdx.x * 64;
    int tid = threadIdx.x;
    int tx = tid & 15, ty = tid >> 4;

    float acc[4][4] = {};
    for (int kb = 0; kb < KZ; kb += GK) {
        int kc = min(GK, KZ - kb);
        __syncthreads();
        for (int i = tid; i < kc * 64; i += 256) {
            int k = i >> 6, m = i & 63;
            As[k * TS + m] = d_Ut[(kb + k) * MR + mb + m];
            int row = kb + k;
            const float* src = (row < 3) ? (xyz + ((size_t)b * 3 + row) * NP)
                                         : (feature + ((size_t)b * CC + (row - 3)) * NP);
            Zs[k * TS + m] = src[nb + m];
        }
        __syncthreads();
        #pragma unroll 4
        for (int k = 0; k < kc; ++k) {
            float4 a4 = *(const float4*)(As + k * TS + ty * 4);
            float4 z4 = *(const float4*)(Zs + k * TS + tx * 4);
            float ar[4] = {a4.x, a4.y, a4.z, a4.w};
            float zr[4] = {z4.x, z4.y, z4.z, z4.w};
            #pragma unroll
            for (int i2 = 0; i2 < 4; i2++)
                #pragma unroll
                for (int j2 = 0; j2 < 4; j2++)
                    acc[i2][j2] = fmaf(zr[i2], ar[j2], acc[i2][j2]);
        }
    }
    float4 ub4 = *(const float4*)(d_Ub + mb + ty * 4);
    #pragma unroll
    for (int i2 = 0; i2 < 4; i2++) {
        float4 o4;
        o4.x = acc[i2][0] + ub4.x;
        o4.y = acc[i2][1] + ub4.y;
        o4.z = acc[i2][2] + ub4.z;
        o4.w = acc[i2][3] + ub4.w;
        size_t n = (size_t)b * NP + nb + tx * 4 + i2;
        *(float4*)(d_PS + n * MR + mb + ty * 4) = o4;
    }
}

// ---------------- kernel 2: KNN — warp-distributed sorted top-17, ballot-gated ----------------
#define KTC 1024
__global__ __launch_bounds__(256) void knn_kernel(const float* __restrict__ xyz) {
    __shared__ float4 cand[KTC];
    int b    = blockIdx.y;
    int tid  = threadIdx.x;
    int warp = tid >> 5;
    int lane = tid & 31;
    int n    = blockIdx.x * 8 + warp;

    const float* xb = xyz + (size_t)b * 3 * NP;
    float qx = __ldg(xb + n), qy = __ldg(xb + NP + n), qz = __ldg(xb + 2 * NP + n);

    const float INFF = __int_as_float(0x7f800000);
    float v = INFF;        // lane l (l<17) holds rank-l key (ascending)
    int   vi = 0x7fffffff;
    float tau = INFF;      // rank-16 key, warp-uniform

    for (int t = 0; t < NP / KTC; t++) {
        int base = t * KTC;
        for (int i = tid; i < KTC; i += 256) {
            int c = base + i;
            float x = __ldg(xb + c), y = __ldg(xb + NP + c), z = __ldg(xb + 2 * NP + c);
            float sq = fmaf(x, x, fmaf(y, y, z * z));
            cand[i] = make_float4(x, y, z, sq);
        }
        __syncthreads();
        for (int s = 0; s < KTC / 32; s++) {
            int ci = base + s * 32 + lane;
            float4 cd = cand[s * 32 + lane];
            float dot = fmaf(cd.x, qx, fmaf(cd.y, qy, cd.z * qz));
            float key = fmaf(-2.0f, dot, cd.w);     // sq[m] - 2*dot (same ranking as ref)
            unsigned mask = __ballot_sync(FULLM, key < tau);
            while (mask) {                           // bounded: popcount(mask) iters max
                int src = __ffs(mask) - 1;
                mask &= mask - 1;
                float kk = __shfl_sync(FULLM, key, src);
                int   kc = __shfl_sync(FULLM, ci, src);
                if (kk < tau) {                      // recheck: tau tightened by prior inserts
                    unsigned pm = __ballot_sync(FULLM, (lane < 17) && (kk < v));
                    int pos = __ffs(pm) - 1;         // first rank whose key > kk
                    float vp = __shfl_up_sync(FULLM, v, 1);
                    int   ip = __shfl_up_sync(FULLM, vi, 1);
                    if (lane < 17 && lane >= pos) {
                        if (lane == pos) { v = kk; vi = kc; }
                        else             { v = vp; vi = ip; }
                    }
                    tau = __shfl_sync(FULLM, v, 16);
                }
            }
        }
        __syncthreads();
    }
    if (lane >= 1 && lane < 17)                      // rank 0 == self, dropped
        d_knn[((size_t)b * NP + n) * KN1 + (lane - 1)] = vi;
}

// ---------------- kernel 3: attention -> res (1 block / point; warp0 2x2 dot tiling) ----------------
__global__ __launch_bounds__(128) void attn_kernel(float* __restrict__ resout) {
    __shared__ float4 qsm[8][17], ksm[16][17], vsm[16][17];
    __shared__ float  S_[192];       // Sq, Sk, Sv
    __shared__ int    idxsm[16];
    __shared__ float  ssm[16];

    int p   = blockIdx.x;           // p = b*NP + f
    int tid = threadIdx.x;
    const float* psb = d_PS + (size_t)p * MR;

    if (tid < 48) ((float4*)S_)[tid] = ((const float4*)(psb + 192))[tid];
    if (tid < 16) idxsm[tid] = d_knn[(size_t)p * KN1 + tid];
    __syncthreads();

    int bbase = (p >> 12) * NP;
    for (int i = tid; i < 640; i += 128) {
        int row = i >> 4, c4 = i & 15;
        if (row < 16) {
            const float4* src = (const float4*)(d_PS + ((size_t)(bbase + idxsm[row])) * MR + 64);
            float4 a = src[c4], s = ((const float4*)(S_ + 64))[c4];
            ksm[row][c4] = make_float4(a.x + s.x, a.y + s.y, a.z + s.z, a.w + s.w);
        } else if (row < 32) {
            int j = row - 16;
            const float4* src = (const float4*)(d_PS + ((size_t)(bbase + idxsm[j])) * MR + 128);
            vsm[j][c4] = src[c4];
        } else {
            int nn = row - 32;
            const float4* src = (const float4*)(d_PS + ((size_t)(bbase + idxsm[nn])) * MR);
            float4 a = src[c4], s = ((const float4*)S_)[c4];
            qsm[nn][c4] = make_float4(a.x + s.x, a.y + s.y, a.z + s.z, a.w + s.w);
        }
    }
    __syncthreads();

    // warp 0: each thread owns attn[2pn..2pn+1][2pj..2pj+1]
    if (tid < 32) {
        int pn = tid >> 3, pj = tid & 7;
        float a00 = 0.f, a01 = 0.f, a10 = 0.f, a11 = 0.f;
        #pragma unroll
        for (int c4 = 0; c4 < 16; c4++) {
            float4 qa = qsm[2 * pn][c4],     qb = qsm[2 * pn + 1][c4];
            float4 ka = ksm[2 * pj][c4],     kb = ksm[2 * pj + 1][c4];
            a00 = fmaf(qa.x, ka.x, a00); a00 = fmaf(qa.y, ka.y, a00);
            a00 = fmaf(qa.z, ka.z, a00); a00 = fmaf(qa.w, ka.w, a00);
            a01 = fmaf(qa.x, kb.x, a01); a01 = fmaf(qa.y, kb.y, a01);
            a01 = fmaf(qa.z, kb.z, a01); a01 = fmaf(qa.w, kb.w, a01);
            a10 = fmaf(qb.x, ka.x, a10); a10 = fmaf(qb.y, ka.y, a10);
            a10 = fmaf(qb.z, ka.z, a10); a10 = fmaf(qb.w, ka.w, a10);
            a11 = fmaf(qb.x, kb.x, a11); a11 = fmaf(qb.y, kb.y, a11);
            a11 = fmaf(qb.z, kb.z, a11); a11 = fmaf(qb.w, kb.w, a11);
        }
        // softmax over j (16 entries per nq row): reduce across pj lanes (bits 1,2,4)
        float m0 = fmaxf(a00, a01), m1 = fmaxf(a10, a11);
        #pragma unroll
        for (int off = 1; off < 8; off <<= 1) {
            m0 = fmaxf(m0, __shfl_xor_sync(FULLM, m0, off));
            m1 = fmaxf(m1, __shfl_xor_sync(FULLM, m1, off));
        }
        float e00 = expf(a00 - m0), e01 = expf(a01 - m0);
        float e10 = expf(a10 - m1), e11 = expf(a11 - m1);
        float s0 = e00 + e01, s1 = e10 + e11;
        #pragma unroll
        for (int off = 1; off < 8; off <<= 1) {
            s0 += __shfl_xor_sync(FULLM, s0, off);
            s1 += __shfl_xor_sync(FULLM, s1, off);
        }
        float inv0 = 1.0f / s0, inv1 = 1.0f / s1;
        // s_j = sum over 8 nq of p[nq][j]: local (nq pair) + reduce across pn lanes (bits 8,16)
        float sj0 = e00 * inv0 + e10 * inv1;   // column j = 2pj
        float sj1 = e01 * inv0 + e11 * inv1;   // column j = 2pj+1
        #pragma unroll
        for (int off = 8; off < 32; off <<= 1) {
            sj0 += __shfl_xor_sync(FULLM, sj0, off);
            sj1 += __shfl_xor_sync(FULLM, sj1, off);
        }
        if (tid < 8) { ssm[2 * tid] = sj0; ssm[2 * tid + 1] = sj1; }
    }
    __syncthreads();

    if (tid < 64) {
        const float* vf = (const float*)vsm;
        float r_ = 8.0f * S_[128 + tid];           // sum_j s_j == 8
        #pragma unroll
        for (int jj = 0; jj < 16; jj++) r_ = fmaf(ssm[jj], vf[jj * 68 + tid], r_);
        resout[(size_t)p * TD + tid] = r_;
    }
}

// ---------------- kernel 4: out = w1 @ res^T + b1 + feature ----------------
#define G2S 68
__global__ __launch_bounds__(256) void gemm2_kernel(const float* __restrict__ w1,
                                                    const float* __restrict__ b1,
                                                    const float* __restrict__ feature,
                                                    float* __restrict__ out) {
    __shared__ float As[TD * G2S];   // [k][c]
    __shared__ float Bs[TD * G2S];   // [k][n]
    int tid = threadIdx.x;
    int cb  = blockIdx.y * 64;
    int gp  = blockIdx.x * 64;       // global point base (64 | 4096 -> single batch)
    int tx = tid & 15, ty = tid >> 4;

    for (int i = tid; i < 64 * 64; i += 256) {
        int c = i & 63, k = i >> 6;
        As[k * G2S + c] = w1[(cb + c) * TD + k];
    }
    for (int i = tid; i < 64 * 16; i += 256) {
        int n = i >> 4, m4 = i & 15;
        float4 r4 = *(const float4*)(d_res + ((size_t)(gp + n)) * TD + m4 * 4);
        Bs[(m4 * 4 + 0) * G2S + n] = r4.x;
        Bs[(m4 * 4 + 1) * G2S + n] = r4.y;
        Bs[(m4 * 4 + 2) * G2S + n] = r4.z;
        Bs[(m4 * 4 + 3) * G2S + n] = r4.w;
    }
    __syncthreads();

    float acc[4][4] = {};  // [c][n]
    #pragma unroll 8
    for (int k = 0; k < TD; k++) {
        float4 a4 = *(const float4*)(As + k * G2S + ty * 4);
        float4 b4 = *(const float4*)(Bs + k * G2S + tx * 4);
        float ar[4] = {a4.x, a4.y, a4.z, a4.w};
        float br[4] = {b4.x, b4.y, b4.z, b4.w};
        #pragma unroll
        for (int i2 = 0; i2 < 4; i2++)
            #pragma unroll
            for (int j2 = 0; j2 < 4; j2++)
                acc[i2][j2] = fmaf(ar[i2], br[j2], acc[i2][j2]);
    }

    int b = gp >> 12;
    int f0 = (gp & 4095) + tx * 4;
    #pragma unroll
    for (int i2 = 0; i2 < 4; i2++) {
        int c = cb + ty * 4 + i2;
        float bias = __ldg(b1 + c);
        size_t addr = ((size_t)(b * CC + c)) * NP + f0;
        float4 fea = *(const float4*)(feature + addr);
        float4 o4;
        o4.x = acc[i2][0] + bias + fea.x;
        o4.y = acc[i2][1] + bias + fea.y;
        o4.z = acc[i2][2] + bias + fea.z;
        o4.w = acc[i2][3] + bias + fea.w;
        *(float4*)(out + addr) = o4;
    }
}

// ---------------- launch ----------------
extern "C" void kernel_launch(void* const* d_in, const int* in_sizes, int n_in,
                              void* d_out, int out_size) {
    const float* feature = (const float*)d_in[0];
    const float* xyz     = (const float*)d_in[1];
    const float* wq      = (const float*)d_in[2];
    const float* bq      = (const float*)d_in[3];
    const float* wk      = (const float*)d_in[4];
    const float* bk      = (const float*)d_in[5];
    const float* wv      = (const float*)d_in[6];
    const float* bv      = (const float*)d_in[7];
    const float* w1      = (const float*)d_in[8];
    const float* b1      = (const float*)d_in[9];
    float* out = (float*)d_out;

    static cudaStream_t s2 = nullptr;
    static cudaEvent_t  evFork = nullptr, evJoin = nullptr;
    if (s2 == nullptr) {
        cudaStreamCreateWithFlags(&s2, cudaStreamNonBlocking);
        cudaEventCreateWithFlags(&evFork, cudaEventDisableTiming);
        cudaEventCreateWithFlags(&evJoin, cudaEventDisableTiming);
    }

    float* resbuf;
    cudaGetSymbolAddress((void**)&resbuf, d_res);

    // fork: knn runs on s2 concurrently with prep+gemm1 on the main stream
    cudaEventRecord(evFork, 0);
    cudaStreamWaitEvent(s2, evFork, 0);
    knn_kernel<<<dim3(512, 4), 256, 0, s2>>>(xyz);
    cudaEventRecord(evJoin, s2);

    prep_kernel<<<96, 256>>>(wq, bq, wk, bk, wv, bv);
    gemm_kernel<<<dim3(64, 6, 4), 256>>>(xyz, feature);

    // join before attention (needs both PS and knn)
    cudaStreamWaitEvent(0, evJoin, 0);
    attn_kernel<<<BN * NP, 128>>>(resbuf);
    gemm2_kernel<<<dim3(256, 2), 256>>>(w1, b1, feature, out);
}